// round 10
// baseline (speedup 1.0000x reference)
#include <cuda_runtime.h>
#include <cuda_bf16.h>
#include <cstdint>

// ---------------- scratch (device globals; no allocation allowed) ----------
#define MAX_N 100000
#define MAX_E 1600000
#define DF 128

__device__ float g_pooled[(size_t)MAX_N * DF];
__device__ float g_y1[(size_t)MAX_N * DF];
__device__ float g_stats[512];   // zeroed at tail of previous call
__device__ float g_sf1[256];
__device__ float g_sf2[256];

// CSR scratch
__device__ int g_deg[MAX_N + 2];     // zeroed at tail of previous call
__device__ int g_off[MAX_N + 2];
__device__ int g_cur[MAX_N + 2];
__device__ int g_srcsorted[MAX_E];

// lookback-scan state (zeroed at tail of previous call)
__device__ volatile int g_flag[128];
__device__ int g_bsum[128];

// ==================== CSR build ==============================================

__global__ void count_kernel(const int* __restrict__ edst, int E) {
    int i = blockIdx.x * blockDim.x + threadIdx.x;
    if (i < E) atomicAdd(&g_deg[edst[i]], 1);
}

// single-kernel exclusive scan with decoupled lookback (98 blocks, all resident)
__global__ __launch_bounds__(1024)
void scan_lookback_kernel(int total) {
    __shared__ int sm[1024];
    __shared__ int sbase;
    int t = threadIdx.x, b = blockIdx.x;
    int g = b * 1024 + t;
    int x = (g < total) ? g_deg[g] : 0;
    sm[t] = x;
    __syncthreads();
#pragma unroll
    for (int o = 1; o < 1024; o <<= 1) {
        int v = (t >= o) ? sm[t - o] : 0;
        __syncthreads();
        sm[t] += v;
        __syncthreads();
    }
    if (t == 0) {
        int base = 0;
        if (b > 0) {
            while (g_flag[b - 1] == 0) {}
            __threadfence();
            base = g_bsum[b - 1];
        }
        sbase = base;
        g_bsum[b] = base + sm[1023];
        __threadfence();
        g_flag[b] = 1;
    }
    __syncthreads();
    int excl = sbase + sm[t] - x;
    if (g < total) {
        g_off[g] = excl;
        g_cur[g] = excl;
    }
}

__global__ void fill_kernel(const int* __restrict__ esrc,
                            const int* __restrict__ edst, int E) {
    int i = blockIdx.x * blockDim.x + threadIdx.x;
    if (i < E) {
        int d = edst[i];
        int pos = atomicAdd(&g_cur[d], 1);
        g_srcsorted[pos] = esrc[i];
    }
}

// ---------------- gather: pooled[i] = (1+eps)*h[i] + sum_{s in nbr(i)} h[s] -

__global__ void gather_kernel(const float4* __restrict__ h4,
                              const float* __restrict__ eps, int N) {
    int gwarp = (blockIdx.x * blockDim.x + threadIdx.x) >> 5;
    if (gwarp >= N) return;
    int lane = threadIdx.x & 31;
    int node = gwarp;

    float c = 1.f + eps[0];
    float4 self = __ldg(&h4[(long long)node * 32 + lane]);
    float4 acc;
    acc.x = self.x * c; acc.y = self.y * c; acc.z = self.z * c; acc.w = self.w * c;

    int begin = g_off[node];
    int end = g_off[node + 1];

    for (int j0 = begin; j0 < end; j0 += 32) {
        int cnt = min(32, end - j0);
        int myIdx = (lane < cnt) ? g_srcsorted[j0 + lane] : 0;
        int t = 0;
        for (; t + 4 <= cnt; t += 4) {
            int s0 = __shfl_sync(0xffffffff, myIdx, t + 0);
            int s1 = __shfl_sync(0xffffffff, myIdx, t + 1);
            int s2 = __shfl_sync(0xffffffff, myIdx, t + 2);
            int s3 = __shfl_sync(0xffffffff, myIdx, t + 3);
            float4 v0 = __ldg(&h4[(long long)s0 * 32 + lane]);
            float4 v1 = __ldg(&h4[(long long)s1 * 32 + lane]);
            float4 v2 = __ldg(&h4[(long long)s2 * 32 + lane]);
            float4 v3 = __ldg(&h4[(long long)s3 * 32 + lane]);
            acc.x += v0.x + v1.x; acc.y += v0.y + v1.y;
            acc.z += v0.z + v1.z; acc.w += v0.w + v1.w;
            acc.x += v2.x + v3.x; acc.y += v2.y + v3.y;
            acc.z += v2.z + v3.z; acc.w += v2.w + v3.w;
        }
        for (; t < cnt; t++) {
            int s = __shfl_sync(0xffffffff, myIdx, t);
            float4 v = __ldg(&h4[(long long)s * 32 + lane]);
            acc.x += v.x; acc.y += v.y; acc.z += v.z; acc.w += v.w;
        }
    }
    reinterpret_cast<float4*>(g_pooled)[(long long)node * 32 + lane] = acc;
}

// ==================== SIMT GEMM + fused BN stats (exact R2 config) ==========
// 256 threads, tile 64 rows x 128 cols, K=128. Natural regs (~138), 1 CTA/SM.
// This configuration measured 116us/GEMM (~83% of FFMA-issue ceiling).

template <bool TRANSFORM>
__global__ __launch_bounds__(256)
void gemm_bias_stats_kernel(const float* __restrict__ A,
                            const float* __restrict__ W,
                            const float* __restrict__ bias,
                            const float* __restrict__ sf,
                            float* __restrict__ Y,
                            float* __restrict__ gsum,
                            int M) {
    __shared__ float As[64][33];
    __shared__ float Ws[32][128];
    __shared__ float red[8][128];

    int tid = threadIdx.x;
    int cx = tid & 31;
    int ry = tid >> 5;
    int c0 = cx * 4;
    int r0 = ry * 8;
    int rowBase = blockIdx.x * 64;

    float acc[8][4];
#pragma unroll
    for (int i = 0; i < 8; i++)
#pragma unroll
        for (int j = 0; j < 4; j++) acc[i][j] = 0.f;

    for (int kb = 0; kb < 128; kb += 32) {
#pragma unroll
        for (int i = 0; i < 8; i++) {
            int idx = tid + i * 256;
            int r = idx >> 5, k = idx & 31;
            int row = rowBase + r;
            float v = 0.f;
            if (row < M) {
                v = A[(long long)row * 128 + kb + k];
                if (TRANSFORM) {
                    float sc = __ldg(&sf[kb + k]);
                    float sh = __ldg(&sf[128 + kb + k]);
                    v = fmaxf(fmaf(v, sc, sh), 0.f);
                }
            }
            As[r][k] = v;
        }
#pragma unroll
        for (int i = 0; i < 16; i++) {
            int idx = tid + i * 256;
            int k = idx >> 7, c = idx & 127;
            Ws[k][c] = W[(long long)(kb + k) * 128 + c];
        }
        __syncthreads();

#pragma unroll
        for (int k = 0; k < 32; k++) {
            float w[4];
#pragma unroll
            for (int j = 0; j < 4; j++) w[j] = Ws[k][c0 + j];
#pragma unroll
            for (int i = 0; i < 8; i++) {
                float a = As[r0 + i][k];
#pragma unroll
                for (int j = 0; j < 4; j++) acc[i][j] = fmaf(a, w[j], acc[i][j]);
            }
        }
        __syncthreads();
    }

    float bsum[4] = {0.f, 0.f, 0.f, 0.f};
    float bsq[4]  = {0.f, 0.f, 0.f, 0.f};
    float bv[4];
#pragma unroll
    for (int j = 0; j < 4; j++) bv[j] = bias[c0 + j];

#pragma unroll
    for (int i = 0; i < 8; i++) {
        int row = rowBase + r0 + i;
        if (row < M) {
#pragma unroll
            for (int j = 0; j < 4; j++) {
                float y = acc[i][j] + bv[j];
                Y[(long long)row * 128 + c0 + j] = y;
                bsum[j] += y;
                bsq[j]  += y * y;
            }
        }
    }

#pragma unroll
    for (int j = 0; j < 4; j++) red[ry][c0 + j] = bsum[j];
    __syncthreads();
    if (tid < 128) {
        float s = 0.f;
#pragma unroll
        for (int i = 0; i < 8; i++) s += red[i][tid];
        atomicAdd(&gsum[tid], s);
    }
    __syncthreads();
#pragma unroll
    for (int j = 0; j < 4; j++) red[ry][c0 + j] = bsq[j];
    __syncthreads();
    if (tid < 128) {
        float s = 0.f;
#pragma unroll
        for (int i = 0; i < 8; i++) s += red[i][tid];
        atomicAdd(&gsum[128 + tid], s);
    }
}

// ---------------- BN finalize / apply ----------------------------------------

__global__ void finalize_stats_kernel(const float* __restrict__ gsum,
                                      const float* __restrict__ gamma,
                                      const float* __restrict__ beta,
                                      float* __restrict__ sf, float invN) {
    int c = threadIdx.x;
    float mu = gsum[c] * invN;
    float var = gsum[128 + c] * invN - mu * mu;
    float rstd = rsqrtf(var + 1e-5f);
    float scale = gamma[c] * rstd;
    sf[c] = scale;
    sf[128 + c] = fmaf(-mu, scale, beta[c]);
}

// out = relu(out*scale + shift) in place; ALSO resets scratch for next call
__global__ void apply_bn_relu_kernel(float4* __restrict__ out,
                                     const float* __restrict__ sf,
                                     int total4, int degTotal) {
    int i = blockIdx.x * blockDim.x + threadIdx.x;
    if (i < 128) { g_bsum[i] = 0; g_flag[i] = 0; }
    if (i < 512) g_stats[i] = 0.f;
    if (i < degTotal) g_deg[i] = 0;
    if (i >= total4) return;
    int c = (i * 4) & 127;
    float4 v = out[i];
    v.x = fmaxf(fmaf(v.x, sf[c + 0], sf[128 + c + 0]), 0.f);
    v.y = fmaxf(fmaf(v.y, sf[c + 1], sf[128 + c + 1]), 0.f);
    v.z = fmaxf(fmaf(v.z, sf[c + 2], sf[128 + c + 2]), 0.f);
    v.w = fmaxf(fmaf(v.w, sf[c + 3], sf[128 + c + 3]), 0.f);
    out[i] = v;
}

// ---------------- launch -----------------------------------------------------

extern "C" void kernel_launch(void* const* d_in, const int* in_sizes, int n_in,
                              void* d_out, int out_size) {
    const float* h    = (const float*)d_in[0];
    const int*  esrc  = (const int*)d_in[1];
    const int*  edst  = (const int*)d_in[2];
    const float* W1   = (const float*)d_in[3];
    const float* b1   = (const float*)d_in[4];
    const float* g1   = (const float*)d_in[5];
    const float* be1  = (const float*)d_in[6];
    const float* W2   = (const float*)d_in[7];
    const float* b2   = (const float*)d_in[8];
    const float* g2   = (const float*)d_in[9];
    const float* be2  = (const float*)d_in[10];
    const float* eps  = (const float*)d_in[11];

    int N = in_sizes[0] / DF;
    int E = in_sizes[1];
    float* out = (float*)d_out;

    float* pooled = nullptr;
    float* y1 = nullptr;
    float* stats = nullptr;
    float* sf1 = nullptr;
    float* sf2 = nullptr;
    cudaGetSymbolAddress((void**)&pooled, g_pooled);
    cudaGetSymbolAddress((void**)&y1,     g_y1);
    cudaGetSymbolAddress((void**)&stats,  g_stats);
    cudaGetSymbolAddress((void**)&sf1,    g_sf1);
    cudaGetSymbolAddress((void**)&sf2,    g_sf2);

    int total4 = N * (DF / 4);
    int scanTotal = N + 1;
    int NB = (scanTotal + 1023) / 1024;

    // g_deg / g_stats / g_flag / g_bsum are zero here (module load or
    // previous call's tail reset).

    // 1) CSR histogram
    count_kernel<<<(E + 255) / 256, 256>>>(edst, E);
    // 2) exclusive scan (single kernel, lookback)
    scan_lookback_kernel<<<NB, 1024>>>(scanTotal);
    // 3) bucket fill
    fill_kernel<<<(E + 255) / 256, 256>>>(esrc, edst, E);
    // 4) gather-pool                               [launch 4 - PROFILED]
    long long gthreads = (long long)N * 32;
    gather_kernel<<<(int)((gthreads + 255) / 256), 256>>>(
        (const float4*)h, eps, N);

    // 5) y1 = pooled @ W1 + b1 ; fused BN1 stats
    int gblocks = (N + 63) / 64;
    gemm_bias_stats_kernel<false><<<gblocks, 256>>>(
        pooled, W1, b1, nullptr, y1, stats, N);
    // 6) finalize BN1
    finalize_stats_kernel<<<1, 128>>>(stats, g1, be1, sf1, 1.f / (float)N);

    // 7) out = relu(bn1(y1)) @ W2 + b2 ; fused BN2 stats
    gemm_bias_stats_kernel<true><<<gblocks, 256>>>(
        y1, W2, b2, sf1, out, stats + 256, N);
    // 8) finalize BN2
    finalize_stats_kernel<<<1, 128>>>(stats + 256, g2, be2, sf2, 1.f / (float)N);

    // 9) out = relu(bn2(out)) + scratch reset for next call
    apply_bn_relu_kernel<<<(total4 + 255) / 256, 256>>>(
        (float4*)out, sf2, total4, scanTotal);
}

// round 11
// speedup vs baseline: 1.4995x; 1.4995x over previous
#include <cuda_runtime.h>
#include <cuda_bf16.h>
#include <cstdint>

// ---------------- scratch (device globals; no allocation allowed) ----------
#define MAX_N 100000
#define MAX_E 1600000
#define DF 128

__device__ float g_pooled[(size_t)MAX_N * DF];
__device__ float g_y1[(size_t)MAX_N * DF];
__device__ float g_stats[512];   // zeroed at tail of previous call
__device__ float g_sf1[256];
__device__ float g_sf2[256];

// CSR scratch
__device__ int g_deg[MAX_N + 2];     // zeroed at tail of previous call
__device__ int g_off[MAX_N + 2];
__device__ int g_cur[MAX_N + 2];
__device__ int g_blocksum[256];      // overwritten fresh each call
__device__ int g_srcsorted[MAX_E];

// ==================== CSR build ==============================================

__global__ void count_kernel(const int* __restrict__ edst, int E) {
    int i = blockIdx.x * blockDim.x + threadIdx.x;
    if (i < E) atomicAdd(&g_deg[edst[i]], 1);
}

// per-1024-chunk sums (measured 6.2us)
__global__ void scan_block_sums(int total) {
    __shared__ int sdata[256];
    int b = blockIdx.x;
    int base = b * 1024;
    int t = threadIdx.x;
    int s = 0;
    for (int i = t; i < 1024; i += 256) {
        int g = base + i;
        s += (g < total) ? g_deg[g] : 0;
    }
    sdata[t] = s;
    __syncthreads();
    for (int o = 128; o > 0; o >>= 1) {
        if (t < o) sdata[t] += sdata[t + o];
        __syncthreads();
    }
    if (t == 0) g_blocksum[b] = sdata[0];
}

// merged final scan: each block independently sums its blocksum prefix
// (parallel, no inter-block wait; measured 5.9us)
__global__ __launch_bounds__(1024)
void scan_final(int total) {
    __shared__ int sm[1024];
    __shared__ int sbase;
    int t = threadIdx.x;
    int b = blockIdx.x;
    if (t == 0) sbase = 0;
    __syncthreads();
    if (t < b) atomicAdd(&sbase, g_blocksum[t]);
    int g = b * 1024 + t;
    int x = (g < total) ? g_deg[g] : 0;
    sm[t] = x;
    __syncthreads();
#pragma unroll
    for (int o = 1; o < 1024; o <<= 1) {
        int v = (t >= o) ? sm[t - o] : 0;
        __syncthreads();
        sm[t] += v;
        __syncthreads();
    }
    int excl = sbase + sm[t] - x;
    if (g < total) {
        g_off[g] = excl;
        g_cur[g] = excl;
    }
}

__global__ void fill_kernel(const int* __restrict__ esrc,
                            const int* __restrict__ edst, int E) {
    int i = blockIdx.x * blockDim.x + threadIdx.x;
    if (i < E) {
        int d = edst[i];
        int pos = atomicAdd(&g_cur[d], 1);
        g_srcsorted[pos] = esrc[i];
    }
}

// ---------------- gather: pooled[i] = (1+eps)*h[i] + sum_{s in nbr(i)} h[s] -

__global__ void gather_kernel(const float4* __restrict__ h4,
                              const float* __restrict__ eps, int N) {
    int gwarp = (blockIdx.x * blockDim.x + threadIdx.x) >> 5;
    if (gwarp >= N) return;
    int lane = threadIdx.x & 31;
    int node = gwarp;

    float c = 1.f + eps[0];
    float4 self = __ldg(&h4[(long long)node * 32 + lane]);
    float4 acc;
    acc.x = self.x * c; acc.y = self.y * c; acc.z = self.z * c; acc.w = self.w * c;

    int begin = g_off[node];
    int end = g_off[node + 1];

    for (int j0 = begin; j0 < end; j0 += 32) {
        int cnt = min(32, end - j0);
        int myIdx = (lane < cnt) ? g_srcsorted[j0 + lane] : 0;
        int t = 0;
        for (; t + 4 <= cnt; t += 4) {
            int s0 = __shfl_sync(0xffffffff, myIdx, t + 0);
            int s1 = __shfl_sync(0xffffffff, myIdx, t + 1);
            int s2 = __shfl_sync(0xffffffff, myIdx, t + 2);
            int s3 = __shfl_sync(0xffffffff, myIdx, t + 3);
            float4 v0 = __ldg(&h4[(long long)s0 * 32 + lane]);
            float4 v1 = __ldg(&h4[(long long)s1 * 32 + lane]);
            float4 v2 = __ldg(&h4[(long long)s2 * 32 + lane]);
            float4 v3 = __ldg(&h4[(long long)s3 * 32 + lane]);
            acc.x += v0.x + v1.x; acc.y += v0.y + v1.y;
            acc.z += v0.z + v1.z; acc.w += v0.w + v1.w;
            acc.x += v2.x + v3.x; acc.y += v2.y + v3.y;
            acc.z += v2.z + v3.z; acc.w += v2.w + v3.w;
        }
        for (; t < cnt; t++) {
            int s = __shfl_sync(0xffffffff, myIdx, t);
            float4 v = __ldg(&h4[(long long)s * 32 + lane]);
            acc.x += v.x; acc.y += v.y; acc.z += v.z; acc.w += v.w;
        }
    }
    reinterpret_cast<float4*>(g_pooled)[(long long)node * 32 + lane] = acc;
}

// ==================== SIMT GEMM + fused BN stats (R9 config: fastest) ========
// 256 threads, tile 64x128, K=128, launch_bounds(256,2) -> reg cap 128,
// 2 CTAs/SM. Measured (R9 vs R10 A/B): ~18us/GEMM faster than natural regs.

template <bool TRANSFORM>
__global__ __launch_bounds__(256, 2)
void gemm_bias_stats_kernel(const float* __restrict__ A,
                            const float* __restrict__ W,
                            const float* __restrict__ bias,
                            const float* __restrict__ sf,
                            float* __restrict__ Y,
                            float* __restrict__ gsum,
                            int M) {
    __shared__ float As[64][33];
    __shared__ float Ws[32][128];
    __shared__ float red[8][128];
    __shared__ float ssf[256];

    int tid = threadIdx.x;
    int cx = tid & 31;
    int ry = tid >> 5;
    int c0 = cx * 4;
    int r0 = ry * 8;
    int rowBase = blockIdx.x * 64;

    if (TRANSFORM) {
        ssf[tid] = sf[tid];
        __syncthreads();
    }

    float acc[8][4];
#pragma unroll
    for (int i = 0; i < 8; i++)
#pragma unroll
        for (int j = 0; j < 4; j++) acc[i][j] = 0.f;

    for (int kb = 0; kb < 128; kb += 32) {
#pragma unroll
        for (int i = 0; i < 8; i++) {
            int idx = tid + i * 256;
            int r = idx >> 5, k = idx & 31;
            int row = rowBase + r;
            float v = 0.f;
            if (row < M) {
                v = A[(long long)row * 128 + kb + k];
                if (TRANSFORM) {
                    v = fmaxf(fmaf(v, ssf[kb + k], ssf[128 + kb + k]), 0.f);
                }
            }
            As[r][k] = v;
        }
#pragma unroll
        for (int i = 0; i < 16; i++) {
            int idx = tid + i * 256;
            int k = idx >> 7, c = idx & 127;
            Ws[k][c] = W[(long long)(kb + k) * 128 + c];
        }
        __syncthreads();

#pragma unroll
        for (int k = 0; k < 32; k++) {
            float w[4];
#pragma unroll
            for (int j = 0; j < 4; j++) w[j] = Ws[k][c0 + j];
#pragma unroll
            for (int i = 0; i < 8; i++) {
                float a = As[r0 + i][k];
#pragma unroll
                for (int j = 0; j < 4; j++) acc[i][j] = fmaf(a, w[j], acc[i][j]);
            }
        }
        __syncthreads();
    }

    float bsum[4] = {0.f, 0.f, 0.f, 0.f};
    float bsq[4]  = {0.f, 0.f, 0.f, 0.f};
    float bv[4];
#pragma unroll
    for (int j = 0; j < 4; j++) bv[j] = bias[c0 + j];

#pragma unroll
    for (int i = 0; i < 8; i++) {
        int row = rowBase + r0 + i;
        if (row < M) {
#pragma unroll
            for (int j = 0; j < 4; j++) {
                float y = acc[i][j] + bv[j];
                Y[(long long)row * 128 + c0 + j] = y;
                bsum[j] += y;
                bsq[j]  += y * y;
            }
        }
    }

#pragma unroll
    for (int j = 0; j < 4; j++) red[ry][c0 + j] = bsum[j];
    __syncthreads();
    if (tid < 128) {
        float s = 0.f;
#pragma unroll
        for (int i = 0; i < 8; i++) s += red[i][tid];
        atomicAdd(&gsum[tid], s);
    }
    __syncthreads();
#pragma unroll
    for (int j = 0; j < 4; j++) red[ry][c0 + j] = bsq[j];
    __syncthreads();
    if (tid < 128) {
        float s = 0.f;
#pragma unroll
        for (int i = 0; i < 8; i++) s += red[i][tid];
        atomicAdd(&gsum[128 + tid], s);
    }
}

// ---------------- BN finalize / apply ----------------------------------------

__global__ void finalize_stats_kernel(const float* __restrict__ gsum,
                                      const float* __restrict__ gamma,
                                      const float* __restrict__ beta,
                                      float* __restrict__ sf, float invN) {
    int c = threadIdx.x;
    float mu = gsum[c] * invN;
    float var = gsum[128 + c] * invN - mu * mu;
    float rstd = rsqrtf(var + 1e-5f);
    float scale = gamma[c] * rstd;
    sf[c] = scale;
    sf[128 + c] = fmaf(-mu, scale, beta[c]);
}

// out = relu(out*scale + shift) in place; ALSO resets scratch for next call
__global__ void apply_bn_relu_kernel(float4* __restrict__ out,
                                     const float* __restrict__ sf,
                                     int total4, int degTotal) {
    int i = blockIdx.x * blockDim.x + threadIdx.x;
    if (i < 512) g_stats[i] = 0.f;
    if (i < degTotal) g_deg[i] = 0;
    if (i >= total4) return;
    int c = (i * 4) & 127;
    float4 v = out[i];
    v.x = fmaxf(fmaf(v.x, sf[c + 0], sf[128 + c + 0]), 0.f);
    v.y = fmaxf(fmaf(v.y, sf[c + 1], sf[128 + c + 1]), 0.f);
    v.z = fmaxf(fmaf(v.z, sf[c + 2], sf[128 + c + 2]), 0.f);
    v.w = fmaxf(fmaf(v.w, sf[c + 3], sf[128 + c + 3]), 0.f);
    out[i] = v;
}

// ---------------- launch -----------------------------------------------------

extern "C" void kernel_launch(void* const* d_in, const int* in_sizes, int n_in,
                              void* d_out, int out_size) {
    const float* h    = (const float*)d_in[0];
    const int*  esrc  = (const int*)d_in[1];
    const int*  edst  = (const int*)d_in[2];
    const float* W1   = (const float*)d_in[3];
    const float* b1   = (const float*)d_in[4];
    const float* g1   = (const float*)d_in[5];
    const float* be1  = (const float*)d_in[6];
    const float* W2   = (const float*)d_in[7];
    const float* b2   = (const float*)d_in[8];
    const float* g2   = (const float*)d_in[9];
    const float* be2  = (const float*)d_in[10];
    const float* eps  = (const float*)d_in[11];

    int N = in_sizes[0] / DF;
    int E = in_sizes[1];
    float* out = (float*)d_out;

    float* pooled = nullptr;
    float* y1 = nullptr;
    float* stats = nullptr;
    float* sf1 = nullptr;
    float* sf2 = nullptr;
    cudaGetSymbolAddress((void**)&pooled, g_pooled);
    cudaGetSymbolAddress((void**)&y1,     g_y1);
    cudaGetSymbolAddress((void**)&stats,  g_stats);
    cudaGetSymbolAddress((void**)&sf1,    g_sf1);
    cudaGetSymbolAddress((void**)&sf2,    g_sf2);

    int total4 = N * (DF / 4);
    int scanTotal = N + 1;
    int NB = (scanTotal + 1023) / 1024;

    // g_deg / g_stats are zero here (module load or previous call's tail reset)

    // 1) CSR histogram
    count_kernel<<<(E + 255) / 256, 256>>>(edst, E);
    // 2) scan: chunk sums, then merged final scan (both parallel, measured fast)
    scan_block_sums<<<NB, 256>>>(scanTotal);
    scan_final<<<NB, 1024>>>(scanTotal);
    // 3) bucket fill                               [launch 4 - PROFILED]
    fill_kernel<<<(E + 255) / 256, 256>>>(esrc, edst, E);
    // 4) gather-pool
    long long gthreads = (long long)N * 32;
    gather_kernel<<<(int)((gthreads + 255) / 256), 256>>>(
        (const float4*)h, eps, N);

    // 5) y1 = pooled @ W1 + b1 ; fused BN1 stats
    int gblocks = (N + 63) / 64;
    gemm_bias_stats_kernel<false><<<gblocks, 256>>>(
        pooled, W1, b1, nullptr, y1, stats, N);
    // 6) finalize BN1
    finalize_stats_kernel<<<1, 128>>>(stats, g1, be1, sf1, 1.f / (float)N);

    // 7) out = relu(bn1(y1)) @ W2 + b2 ; fused BN2 stats
    gemm_bias_stats_kernel<true><<<gblocks, 256>>>(
        y1, W2, b2, sf1, out, stats + 256, N);
    // 8) finalize BN2
    finalize_stats_kernel<<<1, 128>>>(stats + 256, g2, be2, sf2, 1.f / (float)N);

    // 9) out = relu(bn2(out)) + scratch reset for next call
    apply_bn_relu_kernel<<<(total4 + 255) / 256, 256>>>(
        (float4*)out, sf2, total4, scanTotal);
}